// round 5
// baseline (speedup 1.0000x reference)
#include <cuda_runtime.h>
#include <cuda_bf16.h>

#define N 512
#define D 128
#define A 4             // anchors per block
#define T 1024          // 32 warps -> occ 50%
#define NPOS_MAX 64
#define MARGIN 1.0f
#define EPSF 1e-8f

__device__ double             g_sum;
__device__ unsigned long long g_cnt;
__device__ unsigned int       g_done;

__global__ __launch_bounds__(T, 1) void triplet_k(const float* __restrict__ E,
                                                  const int* __restrict__ lab,
                                                  float* __restrict__ out) {
    __shared__ float        s_ea[A * D];        // 4 anchor vectors
    __shared__ float        s_row[A][N];        // dm rows for the 4 anchors
    __shared__ int          s_lab[N];
    __shared__ short        s_pos[A][NPOS_MAX];
    __shared__ int          s_np[A];
    __shared__ double       s_wsum[T / 32];
    __shared__ unsigned int s_wcnt[T / 32];
    __shared__ int          s_last;

    const int i0  = blockIdx.x * A;
    const int tid = threadIdx.x;

    if (tid < A) s_np[tid] = 0;
    for (int idx = tid; idx < A * D; idx += T) s_ea[idx] = E[i0 * D + idx];
    for (int j = tid; j < N; j += T)           s_lab[j]  = lab[j];
    __syncthreads();

    // ---- dot phase: lane pair (2*j, 2*j+1) owns column j; each lane does half of D ----
    {
        const int j    = tid >> 1;              // 0..511
        const int half = tid & 1;               // 0 or 1
        const int Q    = D / 8;                 // 16 float4 per half

        const float4* ej  = (const float4*)(E + j * D) + half * Q;
        const float4* ea4 = (const float4*)s_ea + half * Q;

        float acc0 = 0.f, acc1 = 0.f, acc2 = 0.f, acc3 = 0.f;
#pragma unroll 4
        for (int q = 0; q < Q; q++) {
            const float4 b  = ej[q];
            const float4 a0 = ea4[0 * (D / 4) + q];
            const float4 a1 = ea4[1 * (D / 4) + q];
            const float4 a2 = ea4[2 * (D / 4) + q];
            const float4 a3 = ea4[3 * (D / 4) + q];
            acc0 = fmaf(a0.x, b.x, acc0); acc0 = fmaf(a0.y, b.y, acc0);
            acc0 = fmaf(a0.z, b.z, acc0); acc0 = fmaf(a0.w, b.w, acc0);
            acc1 = fmaf(a1.x, b.x, acc1); acc1 = fmaf(a1.y, b.y, acc1);
            acc1 = fmaf(a1.z, b.z, acc1); acc1 = fmaf(a1.w, b.w, acc1);
            acc2 = fmaf(a2.x, b.x, acc2); acc2 = fmaf(a2.y, b.y, acc2);
            acc2 = fmaf(a2.z, b.z, acc2); acc2 = fmaf(a2.w, b.w, acc2);
            acc3 = fmaf(a3.x, b.x, acc3); acc3 = fmaf(a3.y, b.y, acc3);
            acc3 = fmaf(a3.z, b.z, acc3); acc3 = fmaf(a3.w, b.w, acc3);
        }
        // combine halves (partner is the adjacent lane)
        acc0 += __shfl_xor_sync(0xffffffffu, acc0, 1);
        acc1 += __shfl_xor_sync(0xffffffffu, acc1, 1);
        acc2 += __shfl_xor_sync(0xffffffffu, acc2, 1);
        acc3 += __shfl_xor_sync(0xffffffffu, acc3, 1);

        if (half == 0) {
            s_row[0][j] = acc0; s_row[1][j] = acc1;
            s_row[2][j] = acc2; s_row[3][j] = acc3;

            const int lj = s_lab[j];
#pragma unroll
            for (int a = 0; a < A; a++) {
                if (j != i0 + a && lj == s_lab[i0 + a]) {
                    int p = atomicAdd(&s_np[a], 1);
                    s_pos[a][p] = (short)j;
                }
            }
        }
    }
    __syncthreads();

    // ---- hinge phase ----
    float lsum = 0.f;
    unsigned int lcnt = 0;
#pragma unroll
    for (int a = 0; a < A; a++) {
        const int labi  = s_lab[i0 + a];
        const int total = s_np[a] << 9;           // np * N
        for (int idx = tid; idx < total; idx += T) {
            const int p = idx >> 9;
            const int k = idx & (N - 1);
            if (s_lab[k] != labi) {
                const float v = s_row[a][s_pos[a][p]] - s_row[a][k] + MARGIN;
                if (v > 0.f)  lsum += v;
                if (v > EPSF) lcnt++;
            }
        }
    }

    // ---- block reduction ----
    double dsum = (double)lsum;
#pragma unroll
    for (int o = 16; o > 0; o >>= 1) {
        dsum += __shfl_down_sync(0xffffffffu, dsum, o);
        lcnt += __shfl_down_sync(0xffffffffu, lcnt, o);
    }
    const int w = tid >> 5, l = tid & 31;
    if (l == 0) { s_wsum[w] = dsum; s_wcnt[w] = lcnt; }
    __syncthreads();

    if (tid == 0) {
        double t = 0.0;
        unsigned int c = 0;
#pragma unroll
        for (int ww = 0; ww < T / 32; ww++) { t += s_wsum[ww]; c += s_wcnt[ww]; }
        if (t != 0.0 || c != 0) {
            atomicAdd(&g_sum, t);
            atomicAdd(&g_cnt, (unsigned long long)c);
        }
        __threadfence();
        const unsigned int d = atomicAdd(&g_done, 1u);
        s_last = (d == gridDim.x - 1);
    }
    __syncthreads();

    // ---- last block finalizes and resets globals (graph-replay safe) ----
    if (s_last && tid == 0) {
        const double             s = atomicAdd(&g_sum, 0.0);
        const unsigned long long c = atomicAdd(&g_cnt, 0ULL);
        out[0] = (float)(s / ((double)c + (double)EPSF));
        g_sum  = 0.0;
        g_cnt  = 0ULL;
        atomicExch(&g_done, 0u);
    }
}

extern "C" void kernel_launch(void* const* d_in, const int* in_sizes, int n_in,
                              void* d_out, int out_size) {
    const float* E   = (const float*)d_in[0];
    const int*   lab = (const int*)d_in[1];
    float*       out = (float*)d_out;

    triplet_k<<<N / A, T>>>(E, lab, out);
}

// round 6
// speedup vs baseline: 1.6061x; 1.6061x over previous
#include <cuda_runtime.h>
#include <cuda_bf16.h>

#define N 512
#define D 128
#define A 4
#define T 1024
#define RS 516          // padded s_row stride (bank-conflict-free)
#define NPOS_MAX 64
#define MARGIN 1.0f
#define EPSF 1e-8f

__device__ double             g_sum;
__device__ unsigned long long g_cnt;
__device__ unsigned int       g_done;

__global__ __launch_bounds__(T, 1) void triplet_k(const float* __restrict__ E,
                                                  const int* __restrict__ lab,
                                                  float* __restrict__ out) {
    __shared__ float        s_row[A * RS];
    __shared__ int          s_lab[N];
    __shared__ short        s_pos[A][NPOS_MAX];
    __shared__ int          s_np[A];
    __shared__ double       s_wsum[T / 32];
    __shared__ unsigned int s_wcnt[T / 32];
    __shared__ int          s_last;

    const int i0   = blockIdx.x * A;
    const int tid  = threadIdx.x;
    const int lane = tid & 31;
    const int w    = tid >> 5;          // 32 warps

    if (tid < A) s_np[tid] = 0;
    if (tid < N) s_lab[tid] = lab[tid];
    __syncthreads();

    // positives (threads 0..511, one j each)
    if (tid < N) {
        const int lj = s_lab[tid];
#pragma unroll
        for (int a = 0; a < A; a++) {
            if (tid != i0 + a && lj == s_lab[i0 + a]) {
                int p = atomicAdd(&s_np[a], 1);
                s_pos[a][p] = (short)tid;
            }
        }
    }

    // anchors in registers: lane l holds elements [4l..4l+3] of each anchor
    const float4 A0 = *(const float4*)(E + (i0 + 0) * D + 4 * lane);
    const float4 A1 = *(const float4*)(E + (i0 + 1) * D + 4 * lane);
    const float4 A2 = *(const float4*)(E + (i0 + 2) * D + 4 * lane);
    const float4 A3 = *(const float4*)(E + (i0 + 3) * D + 4 * lane);

    // ---- dot phase: warp w owns rows [16w, 16w+16); one coalesced LDG.128 per row ----
    const bool b1 = lane & 1;
    const bool b2 = lane & 2;
#pragma unroll
    for (int r = 0; r < 16; r++) {
        const int j = (w << 4) + r;
        const float4 b = *(const float4*)(E + j * D + 4 * lane);

        float c0 = fmaf(b.x, A0.x, fmaf(b.y, A0.y, fmaf(b.z, A0.z, b.w * A0.w)));
        float c1 = fmaf(b.x, A1.x, fmaf(b.y, A1.y, fmaf(b.z, A1.z, b.w * A1.w)));
        float c2 = fmaf(b.x, A2.x, fmaf(b.y, A2.y, fmaf(b.z, A2.z, b.w * A2.w)));
        float c3 = fmaf(b.x, A3.x, fmaf(b.y, A3.y, fmaf(b.z, A3.z, b.w * A3.w)));

        // mixed butterfly: 6 shfls reduce all 4 dots; lane c (0..3) ends with dot c
        float p01 = (b1 ? c1 : c0) + __shfl_xor_sync(0xffffffffu, b1 ? c0 : c1, 1);
        float p23 = (b1 ? c3 : c2) + __shfl_xor_sync(0xffffffffu, b1 ? c2 : c3, 1);
        float q   = (b2 ? p23 : p01) + __shfl_xor_sync(0xffffffffu, b2 ? p01 : p23, 2);
        q += __shfl_xor_sync(0xffffffffu, q, 4);
        q += __shfl_xor_sync(0xffffffffu, q, 8);
        q += __shfl_xor_sync(0xffffffffu, q, 16);

        if (lane < 4) s_row[lane * RS + j] = q;
    }
    __syncthreads();

    // ---- hinge phase ----
    float lsum = 0.f;
    unsigned int lcnt = 0;
#pragma unroll
    for (int a = 0; a < A; a++) {
        const int labi  = s_lab[i0 + a];
        const int total = s_np[a] << 9;       // np * N
        const float* row = s_row + a * RS;
        for (int idx = tid; idx < total; idx += T) {
            const int p = idx >> 9;
            const int k = idx & (N - 1);
            if (s_lab[k] != labi) {
                const float v = row[s_pos[a][p]] - row[k] + MARGIN;
                if (v > 0.f)  lsum += v;
                if (v > EPSF) lcnt++;
            }
        }
    }

    // ---- block reduction ----
    double dsum = (double)lsum;
#pragma unroll
    for (int o = 16; o > 0; o >>= 1) {
        dsum += __shfl_down_sync(0xffffffffu, dsum, o);
        lcnt += __shfl_down_sync(0xffffffffu, lcnt, o);
    }
    if (lane == 0) { s_wsum[w] = dsum; s_wcnt[w] = lcnt; }
    __syncthreads();

    if (tid == 0) {
        double t = 0.0;
        unsigned int c = 0;
#pragma unroll
        for (int ww = 0; ww < T / 32; ww++) { t += s_wsum[ww]; c += s_wcnt[ww]; }
        if (t != 0.0 || c != 0) {
            atomicAdd(&g_sum, t);
            atomicAdd(&g_cnt, (unsigned long long)c);
        }
        __threadfence();
        const unsigned int d = atomicAdd(&g_done, 1u);
        s_last = (d == gridDim.x - 1);
    }
    __syncthreads();

    if (s_last && tid == 0) {
        const double             s = atomicAdd(&g_sum, 0.0);
        const unsigned long long c = atomicAdd(&g_cnt, 0ULL);
        out[0] = (float)(s / ((double)c + (double)EPSF));
        g_sum  = 0.0;
        g_cnt  = 0ULL;
        atomicExch(&g_done, 0u);
    }
}

extern "C" void kernel_launch(void* const* d_in, const int* in_sizes, int n_in,
                              void* d_out, int out_size) {
    const float* E   = (const float*)d_in[0];
    const int*   lab = (const int*)d_in[1];
    float*       out = (float*)d_out;

    triplet_k<<<N / A, T>>>(E, lab, out);
}

// round 7
// speedup vs baseline: 1.6091x; 1.0019x over previous
#include <cuda_runtime.h>
#include <cuda_bf16.h>

#define N 512
#define D 128
#define A 4
#define T 1024
#define RS 516          // padded s_row stride (bank-conflict-free)
#define NPOS_MAX 64
#define MARGIN 1.0f
#define EPSF 1e-8f

__device__ double             g_sum;
__device__ unsigned long long g_cnt;
__device__ unsigned int       g_done;

__global__ __launch_bounds__(T, 1) void triplet_k(const float* __restrict__ E,
                                                  const int* __restrict__ lab,
                                                  float* __restrict__ out) {
    __shared__ float        s_row[A * RS];
    __shared__ float        s_prow[A * NPOS_MAX];   // positive row values, compacted
    __shared__ int          s_lab[N];
    __shared__ short        s_pos[A][NPOS_MAX];
    __shared__ int          s_np[A];
    __shared__ double       s_wsum[T / 32];
    __shared__ unsigned int s_wcnt[T / 32];
    __shared__ int          s_last;

    const int i0   = blockIdx.x * A;
    const int tid  = threadIdx.x;
    const int lane = tid & 31;
    const int w    = tid >> 5;          // 32 warps

    if (tid < A) s_np[tid] = 0;
    if (tid < N) s_lab[tid] = lab[tid];
    __syncthreads();

    // positives (threads 0..511, one j each)
    if (tid < N) {
        const int lj = s_lab[tid];
#pragma unroll
        for (int a = 0; a < A; a++) {
            if (tid != i0 + a && lj == s_lab[i0 + a]) {
                int p = atomicAdd(&s_np[a], 1);
                s_pos[a][p] = (short)tid;
            }
        }
    }

    // anchors in registers: lane l holds elements [4l..4l+3] of each anchor
    const float4 A0 = *(const float4*)(E + (i0 + 0) * D + 4 * lane);
    const float4 A1 = *(const float4*)(E + (i0 + 1) * D + 4 * lane);
    const float4 A2 = *(const float4*)(E + (i0 + 2) * D + 4 * lane);
    const float4 A3 = *(const float4*)(E + (i0 + 3) * D + 4 * lane);

    // ---- dot phase: warp w owns rows [16w, 16w+16); one coalesced LDG.128 per row ----
    const bool b1 = lane & 1;
    const bool b2 = lane & 2;
#pragma unroll
    for (int r = 0; r < 16; r++) {
        const int j = (w << 4) + r;
        const float4 b = *(const float4*)(E + j * D + 4 * lane);

        float c0 = fmaf(b.x, A0.x, fmaf(b.y, A0.y, fmaf(b.z, A0.z, b.w * A0.w)));
        float c1 = fmaf(b.x, A1.x, fmaf(b.y, A1.y, fmaf(b.z, A1.z, b.w * A1.w)));
        float c2 = fmaf(b.x, A2.x, fmaf(b.y, A2.y, fmaf(b.z, A2.z, b.w * A2.w)));
        float c3 = fmaf(b.x, A3.x, fmaf(b.y, A3.y, fmaf(b.z, A3.z, b.w * A3.w)));

        // mixed butterfly: 6 shfls reduce all 4 dots; lane c (0..3) ends with dot c
        float p01 = (b1 ? c1 : c0) + __shfl_xor_sync(0xffffffffu, b1 ? c0 : c1, 1);
        float p23 = (b1 ? c3 : c2) + __shfl_xor_sync(0xffffffffu, b1 ? c2 : c3, 1);
        float q   = (b2 ? p23 : p01) + __shfl_xor_sync(0xffffffffu, b2 ? p01 : p23, 2);
        q += __shfl_xor_sync(0xffffffffu, q, 4);
        q += __shfl_xor_sync(0xffffffffu, q, 8);
        q += __shfl_xor_sync(0xffffffffu, q, 16);

        if (lane < 4) s_row[lane * RS + j] = q;
    }
    __syncthreads();

    // ---- compact positive row values for broadcast access ----
    if (tid < A * NPOS_MAX) {
        const int a = tid >> 6;          // NPOS_MAX == 64
        const int p = tid & 63;
        if (p < s_np[a]) s_prow[(a << 6) + p] = s_row[a * RS + s_pos[a][p]];
    }
    __syncthreads();

    // ---- hinge phase: thread owns k; half-split over positives ----
    float lsum = 0.f;
    unsigned int lcnt = 0;
    {
        const int k    = tid & (N - 1);
        const int h    = tid >> 9;       // 0 or 1
        const int labk = s_lab[k];
        const float r0 = s_row[0 * RS + k];
        const float r1 = s_row[1 * RS + k];
        const float r2 = s_row[2 * RS + k];
        const float r3 = s_row[3 * RS + k];
        const float tv[A] = { MARGIN - r0, MARGIN - r1, MARGIN - r2, MARGIN - r3 };

#pragma unroll
        for (int a = 0; a < A; a++) {
            if (labk != s_lab[i0 + a]) {           // k is a negative for anchor a
                const int    np = s_np[a];
                const float  ta = tv[a];
                const float* pr = s_prow + (a << 6);
                for (int p = h; p < np; p += 2) {
                    const float v = pr[p] + ta;    // row[pos[p]] - row[k] + MARGIN
                    if (v > 0.f)  lsum += v;
                    if (v > EPSF) lcnt++;
                }
            }
        }
    }

    // ---- block reduction ----
    double dsum = (double)lsum;
#pragma unroll
    for (int o = 16; o > 0; o >>= 1) {
        dsum += __shfl_down_sync(0xffffffffu, dsum, o);
        lcnt += __shfl_down_sync(0xffffffffu, lcnt, o);
    }
    if (lane == 0) { s_wsum[w] = dsum; s_wcnt[w] = lcnt; }
    __syncthreads();

    if (tid == 0) {
        double t = 0.0;
        unsigned int c = 0;
#pragma unroll
        for (int ww = 0; ww < T / 32; ww++) { t += s_wsum[ww]; c += s_wcnt[ww]; }
        if (t != 0.0 || c != 0) {
            atomicAdd(&g_sum, t);
            atomicAdd(&g_cnt, (unsigned long long)c);
        }
        __threadfence();
        const unsigned int d = atomicAdd(&g_done, 1u);
        s_last = (d == gridDim.x - 1);
    }
    __syncthreads();

    if (s_last && tid == 0) {
        const double             s = atomicAdd(&g_sum, 0.0);
        const unsigned long long c = atomicAdd(&g_cnt, 0ULL);
        out[0] = (float)(s / ((double)c + (double)EPSF));
        g_sum  = 0.0;
        g_cnt  = 0ULL;
        atomicExch(&g_done, 0u);
    }
}

extern "C" void kernel_launch(void* const* d_in, const int* in_sizes, int n_in,
                              void* d_out, int out_size) {
    const float* E   = (const float*)d_in[0];
    const int*   lab = (const int*)d_in[1];
    float*       out = (float*)d_out;

    triplet_k<<<N / A, T>>>(E, lab, out);
}

// round 8
// speedup vs baseline: 1.8315x; 1.1382x over previous
#include <cuda_runtime.h>
#include <cuda_bf16.h>

#define N 512
#define D 128
#define A 4
#define T 1024
#define RS 520          // s_row stride: 520 % 32 == 8 -> conflict-free STS/LDS patterns
#define NPOS_MAX 64
#define MARGIN 1.0f
#define EPSF 1e-8f

__device__ double             g_sum;
__device__ unsigned long long g_cnt;
__device__ unsigned int       g_done;

__global__ __launch_bounds__(T, 1) void triplet_k(const float* __restrict__ E,
                                                  const int* __restrict__ lab,
                                                  float* __restrict__ out) {
    __shared__ float        s_ea[A * D];          // staged anchors
    __shared__ float        s_row[A * RS];
    __shared__ float        s_prow[A * NPOS_MAX]; // compacted positive row values
    __shared__ int          s_lab[N];
    __shared__ short        s_pos[A][NPOS_MAX];
    __shared__ int          s_np[A];
    __shared__ double       s_wsum[T / 32];
    __shared__ unsigned int s_wcnt[T / 32];
    __shared__ int          s_last;

    const int i0   = blockIdx.x * A;
    const int tid  = threadIdx.x;
    const int lane = tid & 31;
    const int w    = tid >> 5;            // 32 warps

    if (tid < A) s_np[tid] = 0;
    if (tid < A * D) s_ea[tid] = E[i0 * D + tid];   // 2KB coalesced
    if (tid < N)     s_lab[tid] = lab[tid];
    __syncthreads();

    // positives (threads 0..511, one j each)
    if (tid < N) {
        const int lj = s_lab[tid];
#pragma unroll
        for (int a = 0; a < A; a++) {
            if (tid != i0 + a && lj == s_lab[i0 + a]) {
                int p = atomicAdd(&s_np[a], 1);
                s_pos[a][p] = (short)tid;
            }
        }
    }

    // ---- dot phase: warp w owns rows [16w,16w+16); 8-lane group per row ----
    // lane = 8*r + s : row offset r (0..3), segment s (0..7, 16 elems each)
    {
        const int r = lane >> 3;
        const int s = lane & 7;
        const bool b1 = lane & 1;
        const bool b2 = lane & 2;

#pragma unroll
        for (int pass = 0; pass < 4; pass++) {
            const int j = (w << 4) + (pass << 2) + r;
            const float* ejp = E + j * D + s * 4;
            const float* eap = s_ea + s * 4;

            float c0 = 0.f, c1 = 0.f, c2 = 0.f, c3 = 0.f;
#pragma unroll
            for (int q = 0; q < 4; q++) {
                const float4 b  = *(const float4*)(ejp + q * 32);
                const float4 a0 = *(const float4*)(eap + 0 * D + q * 32);
                const float4 a1 = *(const float4*)(eap + 1 * D + q * 32);
                const float4 a2 = *(const float4*)(eap + 2 * D + q * 32);
                const float4 a3 = *(const float4*)(eap + 3 * D + q * 32);
                c0 = fmaf(b.x, a0.x, c0); c0 = fmaf(b.y, a0.y, c0);
                c0 = fmaf(b.z, a0.z, c0); c0 = fmaf(b.w, a0.w, c0);
                c1 = fmaf(b.x, a1.x, c1); c1 = fmaf(b.y, a1.y, c1);
                c1 = fmaf(b.z, a1.z, c1); c1 = fmaf(b.w, a1.w, c1);
                c2 = fmaf(b.x, a2.x, c2); c2 = fmaf(b.y, a2.y, c2);
                c2 = fmaf(b.z, a2.z, c2); c2 = fmaf(b.w, a2.w, c2);
                c3 = fmaf(b.x, a3.x, c3); c3 = fmaf(b.y, a3.y, c3);
                c3 = fmaf(b.z, a3.z, c3); c3 = fmaf(b.w, a3.w, c3);
            }
            // reduce over the 8-lane group: packed xor1, xor2, plain xor4
            float p01 = (b1 ? c1 : c0) + __shfl_xor_sync(0xffffffffu, b1 ? c0 : c1, 1);
            float p23 = (b1 ? c3 : c2) + __shfl_xor_sync(0xffffffffu, b1 ? c2 : c3, 1);
            float qv  = (b2 ? p23 : p01) + __shfl_xor_sync(0xffffffffu, b2 ? p01 : p23, 2);
            qv += __shfl_xor_sync(0xffffffffu, qv, 4);
            // lane (8r + c), c<4, holds dot(anchor c, row j)
            if ((lane & 4) == 0)
                s_row[(lane & 3) * RS + j] = qv;
        }
    }
    __syncthreads();

    // ---- compact positive row values for broadcast access ----
    if (tid < A * NPOS_MAX) {
        const int a = tid >> 6;
        const int p = tid & 63;
        if (p < s_np[a]) s_prow[(a << 6) + p] = s_row[a * RS + s_pos[a][p]];
    }
    __syncthreads();

    // ---- hinge phase: thread owns k; half-split over positives ----
    float lsum = 0.f;
    unsigned int lcnt = 0;
    {
        const int k    = tid & (N - 1);
        const int h    = tid >> 9;
        const int labk = s_lab[k];
        const float tv[A] = { MARGIN - s_row[0 * RS + k], MARGIN - s_row[1 * RS + k],
                              MARGIN - s_row[2 * RS + k], MARGIN - s_row[3 * RS + k] };

#pragma unroll
        for (int a = 0; a < A; a++) {
            if (labk != s_lab[i0 + a]) {
                const int    np = s_np[a];
                const float  ta = tv[a];
                const float* pr = s_prow + (a << 6);
                for (int p = h; p < np; p += 2) {
                    const float v = pr[p] + ta;
                    if (v > 0.f)  lsum += v;
                    if (v > EPSF) lcnt++;
                }
            }
        }
    }

    // ---- block reduction ----
    double dsum = (double)lsum;
#pragma unroll
    for (int o = 16; o > 0; o >>= 1) {
        dsum += __shfl_down_sync(0xffffffffu, dsum, o);
        lcnt += __shfl_down_sync(0xffffffffu, lcnt, o);
    }
    if (lane == 0) { s_wsum[w] = dsum; s_wcnt[w] = lcnt; }
    __syncthreads();

    if (tid == 0) {
        double t = 0.0;
        unsigned int c = 0;
#pragma unroll
        for (int ww = 0; ww < T / 32; ww++) { t += s_wsum[ww]; c += s_wcnt[ww]; }
        if (t != 0.0 || c != 0) {
            atomicAdd(&g_sum, t);
            atomicAdd(&g_cnt, (unsigned long long)c);
        }
        __threadfence();
        const unsigned int d = atomicAdd(&g_done, 1u);
        s_last = (d == gridDim.x - 1);
    }
    __syncthreads();

    if (s_last && tid == 0) {
        const double             s = atomicAdd(&g_sum, 0.0);
        const unsigned long long c = atomicAdd(&g_cnt, 0ULL);
        out[0] = (float)(s / ((double)c + (double)EPSF));
        g_sum  = 0.0;
        g_cnt  = 0ULL;
        atomicExch(&g_done, 0u);
    }
}

extern "C" void kernel_launch(void* const* d_in, const int* in_sizes, int n_in,
                              void* d_out, int out_size) {
    const float* E   = (const float*)d_in[0];
    const int*   lab = (const int*)d_in[1];
    float*       out = (float*)d_out;

    triplet_k<<<N / A, T>>>(E, lab, out);
}